// round 6
// baseline (speedup 1.0000x reference)
#include <cuda_runtime.h>
#include <math.h>

#define C_DIM 128
#define S_DIM 4096
#define HW 176          // 16 * 11
#define HW4 44          // HW / 4
#define B_SEG 32
#define O_DIM 256
#define OTILE 8
#define CPIPE 8         // c-chunk depth for software pipeline
#define PART_LEN 44     // 4 rows * 11
#define GEM_EPS 1e-6f
#define NEG_INF -3.402823466e38f

// scratch: pooled[b][c][hw]
__device__ float g_pooled[B_SEG * C_DIM * HW];

__device__ __forceinline__ float4 max4(float4 a, float4 b) {
    float4 r;
    r.x = fmaxf(a.x, b.x); r.y = fmaxf(a.y, b.y);
    r.z = fmaxf(a.z, b.z); r.w = fmaxf(a.w, b.w);
    return r;
}

// packed fp32x2 helpers (Blackwell FFMA2 path)
__device__ __forceinline__ unsigned long long pack2(float v) {
    unsigned long long r;
    asm("mov.b64 %0, {%1, %1};" : "=l"(r) : "f"(v));
    return r;
}
__device__ __forceinline__ void unpack2(unsigned long long v, float& lo, float& hi) {
    asm("mov.b64 {%0, %1}, %2;" : "=f"(lo), "=f"(hi) : "l"(v));
}
__device__ __forceinline__ void ffma2(unsigned long long& d,
                                      unsigned long long a, unsigned long long b) {
    asm("fma.rn.f32x2 %0, %1, %2, %0;" : "+l"(d) : "l"(a), "l"(b));
}

// ---------------------------------------------------------------------------
// Kernel 1: ragged segment max, float4 streaming, evict-first, MLP=8.
// One block per (b, c); 352 threads = 8 s-groups x 44 f4-columns.
// ~6.25 TB/s — near the practical cap.
// ---------------------------------------------------------------------------
__global__ void __launch_bounds__(352) seg_max_kernel(
    const float* __restrict__ x, const int* __restrict__ seqL)
{
    int blk = blockIdx.x;
    int b = blk & (B_SEG - 1);
    int c = blk >> 5;

    __shared__ int sh[2];
    __shared__ float4 sm[8 * HW4];

    if (threadIdx.x == 0) {
        int s0 = 0;
        #pragma unroll
        for (int i = 0; i < B_SEG; i++) s0 += (i < b) ? seqL[i] : 0;
        sh[0] = s0;
        sh[1] = seqL[b];
    }
    __syncthreads();

    int tid = threadIdx.x;
    int sg  = tid / HW4;   // 0..7
    int col = tid % HW4;   // 0..43

    int s0  = sh[0];
    int len = sh[1];

    const float4* bp = reinterpret_cast<const float4*>(x)
                     + (size_t)c * (S_DIM * HW4) + (size_t)s0 * HW4 + col;

    float4 m = make_float4(NEG_INF, NEG_INF, NEG_INF, NEG_INF);
    int s = sg;
    for (; s + 56 < len; s += 64) {
        float4 a0 = __ldcs(&bp[(size_t)(s +  0) * HW4]);
        float4 a1 = __ldcs(&bp[(size_t)(s +  8) * HW4]);
        float4 a2 = __ldcs(&bp[(size_t)(s + 16) * HW4]);
        float4 a3 = __ldcs(&bp[(size_t)(s + 24) * HW4]);
        float4 a4 = __ldcs(&bp[(size_t)(s + 32) * HW4]);
        float4 a5 = __ldcs(&bp[(size_t)(s + 40) * HW4]);
        float4 a6 = __ldcs(&bp[(size_t)(s + 48) * HW4]);
        float4 a7 = __ldcs(&bp[(size_t)(s + 56) * HW4]);
        m = max4(m, max4(max4(max4(a0, a1), max4(a2, a3)),
                         max4(max4(a4, a5), max4(a6, a7))));
    }
    for (; s < len; s += 8) {
        m = max4(m, __ldcs(&bp[(size_t)s * HW4]));
    }

    sm[sg * HW4 + col] = m;
    __syncthreads();

    if (tid < HW4) {
        float4 r = sm[tid];
        #pragma unroll
        for (int g = 1; g < 8; g++) r = max4(r, sm[g * HW4 + tid]);
        reinterpret_cast<float4*>(g_pooled)[(size_t)(b * C_DIM + c) * HW4 + tid] = r;
    }
}

// ---------------------------------------------------------------------------
// Kernel 2: fused 1x1 conv (FFMA2) + GeM, software-pipelined pooled loads.
// Grid (32 o-tiles of 8, 32 b) = 1024 blocks, 192 threads, min 6 blocks/SM
// (reg cap ~56). Per 8-cc chunk: prefetch next 8 pv (8 LDGs in flight),
// then 8 x (2 broadcast LDS.128 + 4 FFMA2).
// ---------------------------------------------------------------------------
__global__ void __launch_bounds__(192, 6) conv_gem_kernel(
    const float* __restrict__ Wmat, const float* __restrict__ p,
    float* __restrict__ out)
{
    __shared__ __align__(16) float ws[C_DIM * OTILE];   // [c][j], 4 KB
    __shared__ float ypow[OTILE * HW];                  // [j][hw], 5.5 KB
    __shared__ float pp[4];

    int b   = blockIdx.y;
    int o0  = blockIdx.x * OTILE;
    int tid = threadIdx.x;
    int hw  = tid;

    if (tid < 4) pp[tid] = p[tid];
    for (int i = tid; i < C_DIM * OTILE; i += 192) {
        int cc = i >> 3;
        int j  = i & (OTILE - 1);
        ws[i] = Wmat[(o0 + j) * C_DIM + cc];
    }
    __syncthreads();

    if (hw < HW) {
        unsigned long long acc[OTILE / 2];
        #pragma unroll
        for (int k = 0; k < OTILE / 2; k++) acc[k] = 0ULL;

        const float* pb = g_pooled + (size_t)b * C_DIM * HW + hw;

        float pv[CPIPE];
        #pragma unroll
        for (int j = 0; j < CPIPE; j++)
            pv[j] = __ldg(&pb[(size_t)j * HW]);

        #pragma unroll
        for (int c0 = 0; c0 < C_DIM; c0 += CPIPE) {
            float nv[CPIPE];
            if (c0 + CPIPE < C_DIM) {
                #pragma unroll
                for (int j = 0; j < CPIPE; j++)
                    nv[j] = __ldg(&pb[(size_t)(c0 + CPIPE + j) * HW]);
            }
            #pragma unroll
            for (int j = 0; j < CPIPE; j++) {
                unsigned long long pv2 = pack2(pv[j]);
                const ulonglong2* wr = reinterpret_cast<const ulonglong2*>(
                    ws + (c0 + j) * OTILE);
                ulonglong2 w0 = wr[0];
                ulonglong2 w1 = wr[1];
                ffma2(acc[0], pv2, w0.x);
                ffma2(acc[1], pv2, w0.y);
                ffma2(acc[2], pv2, w1.x);
                ffma2(acc[3], pv2, w1.y);
            }
            #pragma unroll
            for (int j = 0; j < CPIPE; j++) pv[j] = nv[j];
        }

        int part = hw / PART_LEN;
        float pe = pp[part];
        #pragma unroll
        for (int k = 0; k < OTILE / 2; k++) {
            float lo, hi;
            unpack2(acc[k], lo, hi);
            ypow[(2 * k + 0) * HW + hw] = exp2f(pe * __log2f(fmaxf(lo, GEM_EPS)));
            ypow[(2 * k + 1) * HW + hw] = exp2f(pe * __log2f(fmaxf(hi, GEM_EPS)));
        }
    }
    __syncthreads();

    // 32 threads: one per (o, part)
    if (tid < OTILE * 4) {
        int j    = tid >> 2;
        int part = tid & 3;
        const float* yp = ypow + j * HW + part * PART_LEN;
        float sum = 0.0f;
        #pragma unroll
        for (int k = 0; k < PART_LEN; k++) sum += yp[k];
        float pe = pp[part];
        float mean = sum * (1.0f / (float)PART_LEN);
        float g = (mean > 0.0f) ? exp2f(__log2f(mean) / pe) : 0.0f;
        out[((size_t)b * O_DIM + o0 + j) * 4 + part] = g;
    }
}

extern "C" void kernel_launch(void* const* d_in, const int* in_sizes, int n_in,
                              void* d_out, int out_size)
{
    const float* x    = (const float*)d_in[0];
    const int*   seqL = (const int*)d_in[1];
    const float* Wm   = (const float*)d_in[2];
    const float* p    = (const float*)d_in[3];
    float* out = (float*)d_out;

    seg_max_kernel<<<B_SEG * C_DIM, 352>>>(x, seqL);

    dim3 grid2(O_DIM / OTILE, B_SEG);
    conv_gem_kernel<<<grid2, 192>>>(Wm, p, out);
}

// round 7
// speedup vs baseline: 1.0132x; 1.0132x over previous
#include <cuda_runtime.h>
#include <math.h>

#define C_DIM 128
#define S_DIM 4096
#define HW 176          // 16 * 11
#define HW4 44          // HW / 4
#define B_SEG 32
#define O_DIM 256
#define OTILE 8
#define PART_LEN 44     // 4 rows * 11
#define GEM_EPS 1e-6f
#define NEG_INF -3.402823466e38f

// scratch: pooled[b][c][hw]
__device__ float g_pooled[B_SEG * C_DIM * HW];

__device__ __forceinline__ float4 max4(float4 a, float4 b) {
    float4 r;
    r.x = fmaxf(a.x, b.x); r.y = fmaxf(a.y, b.y);
    r.z = fmaxf(a.z, b.z); r.w = fmaxf(a.w, b.w);
    return r;
}

// packed fp32x2 helpers (Blackwell FFMA2 path)
__device__ __forceinline__ unsigned long long pack2(float v) {
    unsigned long long r;
    asm("mov.b64 %0, {%1, %1};" : "=l"(r) : "f"(v));
    return r;
}
__device__ __forceinline__ void unpack2(unsigned long long v, float& lo, float& hi) {
    asm("mov.b64 {%0, %1}, %2;" : "=f"(lo), "=f"(hi) : "l"(v));
}
__device__ __forceinline__ void ffma2(unsigned long long& d,
                                      unsigned long long a, unsigned long long b) {
    asm("fma.rn.f32x2 %0, %1, %2, %0;" : "+l"(d) : "l"(a), "l"(b));
}

// GeM power: v^pe. Fast path for pe == 6.5 (the dataset value):
// v^6.5 = (v^3)^2 * sqrt(v)  -> 4 FMUL + 1 MUFU instead of 2 MUFU.
__device__ __forceinline__ float gem_pow(float x, float pe, bool fast65) {
    float v = fmaxf(x, GEM_EPS);
    if (fast65) {
        float v3 = v * v * v;
        return v3 * v3 * sqrtf(v);
    }
    return exp2f(pe * __log2f(v));
}

// ---------------------------------------------------------------------------
// Kernel 1: ragged segment max, float4 streaming, evict-first, MLP=8.
// One block per (b, c); 352 threads = 8 s-groups x 44 f4-columns.
// ~6.25 TB/s — near the practical memory cap.
// ---------------------------------------------------------------------------
__global__ void __launch_bounds__(352) seg_max_kernel(
    const float* __restrict__ x, const int* __restrict__ seqL)
{
    int blk = blockIdx.x;
    int b = blk & (B_SEG - 1);
    int c = blk >> 5;

    __shared__ int sh[2];
    __shared__ float4 sm[8 * HW4];

    if (threadIdx.x == 0) {
        int s0 = 0;
        #pragma unroll
        for (int i = 0; i < B_SEG; i++) s0 += (i < b) ? seqL[i] : 0;
        sh[0] = s0;
        sh[1] = seqL[b];
    }
    __syncthreads();

    int tid = threadIdx.x;
    int sg  = tid / HW4;   // 0..7
    int col = tid % HW4;   // 0..43

    int s0  = sh[0];
    int len = sh[1];

    const float4* bp = reinterpret_cast<const float4*>(x)
                     + (size_t)c * (S_DIM * HW4) + (size_t)s0 * HW4 + col;

    float4 m = make_float4(NEG_INF, NEG_INF, NEG_INF, NEG_INF);
    int s = sg;
    for (; s + 56 < len; s += 64) {
        float4 a0 = __ldcs(&bp[(size_t)(s +  0) * HW4]);
        float4 a1 = __ldcs(&bp[(size_t)(s +  8) * HW4]);
        float4 a2 = __ldcs(&bp[(size_t)(s + 16) * HW4]);
        float4 a3 = __ldcs(&bp[(size_t)(s + 24) * HW4]);
        float4 a4 = __ldcs(&bp[(size_t)(s + 32) * HW4]);
        float4 a5 = __ldcs(&bp[(size_t)(s + 40) * HW4]);
        float4 a6 = __ldcs(&bp[(size_t)(s + 48) * HW4]);
        float4 a7 = __ldcs(&bp[(size_t)(s + 56) * HW4]);
        m = max4(m, max4(max4(max4(a0, a1), max4(a2, a3)),
                         max4(max4(a4, a5), max4(a6, a7))));
    }
    for (; s < len; s += 8) {
        m = max4(m, __ldcs(&bp[(size_t)s * HW4]));
    }

    sm[sg * HW4 + col] = m;
    __syncthreads();

    if (tid < HW4) {
        float4 r = sm[tid];
        #pragma unroll
        for (int g = 1; g < 8; g++) r = max4(r, sm[g * HW4 + tid]);
        reinterpret_cast<float4*>(g_pooled)[(size_t)(b * C_DIM + c) * HW4 + tid] = r;
    }
}

// ---------------------------------------------------------------------------
// Kernel 2: fused 1x1 conv (FFMA2) + GeM.
// Grid (32 o-tiles of 8, 32 b) = 1024 blocks, 192 threads.
// FFMA/LDG side is ~5 us and hides; the real cost is the GeM power epilogue
// (MUFU pipe). gem_pow halves the MUFU count for p == 6.5.
// ---------------------------------------------------------------------------
__global__ void __launch_bounds__(192) conv_gem_kernel(
    const float* __restrict__ Wmat, const float* __restrict__ p,
    float* __restrict__ out)
{
    __shared__ __align__(16) float ws[C_DIM * OTILE];   // [c][j], 4 KB
    __shared__ float ypow[OTILE * HW];                  // [j][hw], 5.5 KB
    __shared__ float pp[4];

    int b   = blockIdx.y;
    int o0  = blockIdx.x * OTILE;
    int tid = threadIdx.x;
    int hw  = tid;

    if (tid < 4) pp[tid] = p[tid];
    for (int i = tid; i < C_DIM * OTILE; i += 192) {
        int cc = i >> 3;
        int j  = i & (OTILE - 1);
        ws[i] = Wmat[(o0 + j) * C_DIM + cc];
    }
    __syncthreads();

    if (hw < HW) {
        unsigned long long acc[OTILE / 2];
        #pragma unroll
        for (int k = 0; k < OTILE / 2; k++) acc[k] = 0ULL;

        const float* pb = g_pooled + (size_t)b * C_DIM * HW + hw;

        #pragma unroll 8
        for (int cc = 0; cc < C_DIM; cc++) {
            unsigned long long pv2 = pack2(__ldg(&pb[(size_t)cc * HW]));
            const ulonglong2* wr = reinterpret_cast<const ulonglong2*>(
                ws + cc * OTILE);
            ulonglong2 w0 = wr[0];
            ulonglong2 w1 = wr[1];
            ffma2(acc[0], pv2, w0.x);
            ffma2(acc[1], pv2, w0.y);
            ffma2(acc[2], pv2, w1.x);
            ffma2(acc[3], pv2, w1.y);
        }

        int part = hw / PART_LEN;
        float pe = pp[part];
        bool fast65 = (pe == 6.5f);
        #pragma unroll
        for (int k = 0; k < OTILE / 2; k++) {
            float lo, hi;
            unpack2(acc[k], lo, hi);
            ypow[(2 * k + 0) * HW + hw] = gem_pow(lo, pe, fast65);
            ypow[(2 * k + 1) * HW + hw] = gem_pow(hi, pe, fast65);
        }
    }
    __syncthreads();

    // 32 threads: one per (o, part)
    if (tid < OTILE * 4) {
        int j    = tid >> 2;
        int part = tid & 3;
        const float* yp = ypow + j * HW + part * PART_LEN;
        float sum = 0.0f;
        #pragma unroll
        for (int k = 0; k < PART_LEN; k++) sum += yp[k];
        float pe = pp[part];
        float mean = sum * (1.0f / (float)PART_LEN);
        float g = (mean > 0.0f) ? exp2f(__log2f(mean) / pe) : 0.0f;
        out[((size_t)b * O_DIM + o0 + j) * 4 + part] = g;
    }
}

extern "C" void kernel_launch(void* const* d_in, const int* in_sizes, int n_in,
                              void* d_out, int out_size)
{
    const float* x    = (const float*)d_in[0];
    const int*   seqL = (const int*)d_in[1];
    const float* Wm   = (const float*)d_in[2];
    const float* p    = (const float*)d_in[3];
    float* out = (float*)d_out;

    seg_max_kernel<<<B_SEG * C_DIM, 352>>>(x, seqL);

    dim3 grid2(O_DIM / OTILE, B_SEG);
    conv_gem_kernel<<<grid2, 192>>>(Wm, p, out);
}